// round 13
// baseline (speedup 1.0000x reference)
#include <cuda_runtime.h>
#include <cuda_bf16.h>
#include <cstdint>

// Problem dims
#define B_ 16
#define L_ 512
#define H_ 8
#define E_ 64
#define BH_ (B_ * H_)          // 128

// ===================== helpers =====================
__device__ __forceinline__ uint32_t smem_u32(const void* p) {
    uint32_t a;
    asm("{ .reg .u64 t; cvta.to.shared.u64 t, %1; cvt.u32.u64 %0, t; }"
        : "=r"(a) : "l"(p));
    return a;
}
__device__ __forceinline__ uint32_t bf16x2_of(float v0, float v1) {
    uint32_t r;
    asm("cvt.rn.bf16x2.f32 %0, %1, %2;" : "=r"(r) : "f"(v1), "f"(v0));
    return r;
}
__device__ __forceinline__ uint32_t lds32(uint32_t addr) {
    uint32_t v;
    asm volatile("ld.shared.b32 %0, [%1];" : "=r"(v) : "r"(addr));
    return v;
}
__device__ __forceinline__ void mma16816(float* c, const uint32_t* a, const uint32_t* b) {
    asm volatile(
        "mma.sync.aligned.m16n8k16.row.col.f32.bf16.bf16.f32 "
        "{%0,%1,%2,%3}, {%4,%5,%6,%7}, {%8,%9}, {%0,%1,%2,%3};"
        : "+f"(c[0]), "+f"(c[1]), "+f"(c[2]), "+f"(c[3])
        : "r"(a[0]), "r"(a[1]), "r"(a[2]), "r"(a[3]), "r"(b[0]), "r"(b[1]));
}
__device__ __forceinline__ float exp_acc(float x) {
    float m = __fmul_rn(x, 1.4426950408889634f);
    float t = __fmaf_rn(x, 1.925962991e-8f, m);
    float r;
    asm("ex2.approx.ftz.f32 %0, %1;" : "=f"(r) : "f"(t));
    return r;
}
__device__ __forceinline__ void split_store4(char* smem, uint32_t offHi, uint32_t offLo, float4 v) {
    uint32_t h01 = bf16x2_of(v.x, v.y);
    uint32_t h23 = bf16x2_of(v.z, v.w);
    float l0 = v.x - __uint_as_float(h01 << 16);
    float l1 = v.y - __uint_as_float(h01 & 0xFFFF0000u);
    float l2 = v.z - __uint_as_float(h23 << 16);
    float l3 = v.w - __uint_as_float(h23 & 0xFFFF0000u);
    *(uint2*)(smem + offHi) = make_uint2(h01, h23);
    *(uint2*)(smem + offLo) = make_uint2(bf16x2_of(l0, l1), bf16x2_of(l2, l3));
}
__device__ __forceinline__ void split2(float2 v, uint32_t& hi, uint32_t& lo) {
    hi = bf16x2_of(v.x, v.y);
    float l0 = v.x - __uint_as_float(hi << 16);
    float l1 = v.y - __uint_as_float(hi & 0xFFFF0000u);
    lo = bf16x2_of(l0, l1);
}

// ======================================================================
// Kernel 1 (R6 form, measured 73.8us): series = softmax(QK^T/8).
// CTA: 64 l-rows x 512 s-cols, 512 thr.
// ======================================================================
#define F_ST   72
#define F_QHI  0
#define F_QLO  9216
#define F_KHI  18432
#define F_KLO  92160
#define F_RED0 165888
#define F_RED1 166912
#define F_SMEM 167936

__global__ void __launch_bounds__(512, 1)
qk_softmax_kernel(const float* __restrict__ q, const float* __restrict__ k,
                  float* __restrict__ series)
{
    extern __shared__ char smem[];
    const uint32_t sb = smem_u32(smem);
    const int tid  = threadIdx.x;
    const int wid  = tid >> 5;
    const int lane = tid & 31;
    const int wm   = wid >> 2;
    const int wn   = wid & 3;
    const int r    = lane >> 2;
    const int qc   = lane & 3;

    const int bh = blockIdx.y;
    const int b  = bh >> 3;
    const int h  = bh & 7;
    const int lt = blockIdx.x;

    const float* qbase = q + (size_t)(b * L_ + lt * 64) * (H_ * E_) + h * E_;
    const float* kbase = k + (size_t)(b * L_) * (H_ * E_) + h * E_;

#pragma unroll
    for (int i = tid; i < 1024; i += 512) {
        int row = i >> 4, e4 = i & 15;
        uint32_t off = (uint32_t)row * (F_ST * 2) + e4 * 8;
        float4 va = *(const float4*)(qbase + (size_t)row * (H_ * E_) + e4 * 4);
        va.x *= 0.125f; va.y *= 0.125f; va.z *= 0.125f; va.w *= 0.125f;
        split_store4(smem, F_QHI + off, F_QLO + off, va);
    }
#pragma unroll
    for (int i = tid; i < 8192; i += 512) {
        int row = i >> 4, e4 = i & 15;
        uint32_t off = (uint32_t)row * (F_ST * 2) + e4 * 8;
        float4 vb = *(const float4*)(kbase + (size_t)row * (H_ * E_) + e4 * 4);
        split_store4(smem, F_KHI + off, F_KLO + off, vb);
    }
    __syncthreads();

    float acc[16][4];
#pragma unroll
    for (int nb = 0; nb < 16; nb++)
#pragma unroll
        for (int x = 0; x < 4; x++) acc[nb][x] = 0.f;

    const uint32_t abase[3] = {sb + F_QHI, sb + F_QHI, sb + F_QLO};
    const uint32_t bbase[3] = {sb + F_KHI, sb + F_KLO, sb + F_KHI};

#pragma unroll
    for (int pr = 0; pr < 3; pr++) {
        uint32_t Ab = abase[pr], Bb = bbase[pr];
#pragma unroll
        for (int ks = 0; ks < 4; ks++) {
            uint32_t kByte = ks * 32 + qc * 4;
            uint32_t a[4];
            uint32_t ad = Ab + (uint32_t)(wm * 16 + r) * (F_ST * 2) + kByte;
            a[0] = lds32(ad);
            a[1] = lds32(ad + 8 * F_ST * 2);
            a[2] = lds32(ad + 16);
            a[3] = lds32(ad + 8 * F_ST * 2 + 16);
#pragma unroll
            for (int nb = 0; nb < 16; nb++) {
                uint32_t bd = Bb + (uint32_t)(wn * 128 + nb * 8 + r) * (F_ST * 2) + kByte;
                uint32_t bf[2];
                bf[0] = lds32(bd);
                bf[1] = lds32(bd + 16);
                mma16816(acc[nb], a, bf);
            }
        }
    }

    const int row0 = wm * 16 + r;
    const int row1 = row0 + 8;

    float mx0 = -1e30f, mx1 = -1e30f;
#pragma unroll
    for (int nb = 0; nb < 16; nb++) {
        mx0 = fmaxf(mx0, fmaxf(acc[nb][0], acc[nb][1]));
        mx1 = fmaxf(mx1, fmaxf(acc[nb][2], acc[nb][3]));
    }
#pragma unroll
    for (int o = 1; o <= 2; o <<= 1) {
        mx0 = fmaxf(mx0, __shfl_xor_sync(0xffffffffu, mx0, o));
        mx1 = fmaxf(mx1, __shfl_xor_sync(0xffffffffu, mx1, o));
    }
    if (qc == 0) {
        *(float*)(smem + F_RED0 + (row0 * 4 + wn) * 4) = mx0;
        *(float*)(smem + F_RED0 + (row1 * 4 + wn) * 4) = mx1;
    }
    __syncthreads();
    {
        const float* rd = (const float*)(smem + F_RED0);
        mx0 = fmaxf(fmaxf(rd[row0 * 4 + 0], rd[row0 * 4 + 1]),
                    fmaxf(rd[row0 * 4 + 2], rd[row0 * 4 + 3]));
        mx1 = fmaxf(fmaxf(rd[row1 * 4 + 0], rd[row1 * 4 + 1]),
                    fmaxf(rd[row1 * 4 + 2], rd[row1 * 4 + 3]));
    }

    float s0 = 0.f, s1 = 0.f;
#pragma unroll
    for (int nb = 0; nb < 16; nb++) {
        acc[nb][0] = exp_acc(acc[nb][0] - mx0); s0 += acc[nb][0];
        acc[nb][1] = exp_acc(acc[nb][1] - mx0); s0 += acc[nb][1];
        acc[nb][2] = exp_acc(acc[nb][2] - mx1); s1 += acc[nb][2];
        acc[nb][3] = exp_acc(acc[nb][3] - mx1); s1 += acc[nb][3];
    }
#pragma unroll
    for (int o = 1; o <= 2; o <<= 1) {
        s0 += __shfl_xor_sync(0xffffffffu, s0, o);
        s1 += __shfl_xor_sync(0xffffffffu, s1, o);
    }
    if (qc == 0) {
        *(float*)(smem + F_RED1 + (row0 * 4 + wn) * 4) = s0;
        *(float*)(smem + F_RED1 + (row1 * 4 + wn) * 4) = s1;
    }
    __syncthreads();
    {
        const float* rd = (const float*)(smem + F_RED1);
        s0 = (rd[row0 * 4 + 0] + rd[row0 * 4 + 1]) + (rd[row0 * 4 + 2] + rd[row0 * 4 + 3]);
        s1 = (rd[row1 * 4 + 0] + rd[row1 * 4 + 1]) + (rd[row1 * 4 + 2] + rd[row1 * 4 + 3]);
    }
    const float inv0 = __fdiv_rn(1.f, s0);
    const float inv1 = __fdiv_rn(1.f, s1);

    float* o0 = series + ((size_t)bh * L_ + lt * 64 + row0) * L_ + wn * 128 + qc * 2;
    float* o1 = series + ((size_t)bh * L_ + lt * 64 + row1) * L_ + wn * 128 + qc * 2;
#pragma unroll
    for (int nb = 0; nb < 16; nb++) {
        *(float2*)(o0 + nb * 8) = make_float2(acc[nb][0] * inv0, acc[nb][1] * inv0);
        *(float2*)(o1 + nb * 8) = make_float2(acc[nb][2] * inv1, acc[nb][3] * inv1);
    }
}

// ======================================================================
// Kernel 2 (pv4): V = P @ values  AND prior + sigf for the same bh.
// One CTA per bh: 512 rows x 64 d, 512 thr, warp = 32 rows.
// sg recomputed in prologue (fp64, 1 row/thread). Each mainloop iter ks
// writes the 16-row prior/sigf slice [ks*16, ks*16+16) x 512 cols,
// placed between P loads and MMA so stores/exp hide load latency and
// DRAM drains continuously.
// ======================================================================
#define PVB_ST   1040
#define PVB_HI   0
#define PVB_LO   66560
#define PVB_SG   133120            // 512 * 4
#define PVB_SMEM 135168

__global__ void __launch_bounds__(512, 1)
pv4_kernel(const float* __restrict__ p, const float* __restrict__ v,
           const float* __restrict__ sigma,
           float* __restrict__ out,
           float* __restrict__ prior, float* __restrict__ sigf)
{
    extern __shared__ char smem[];
    const uint32_t sb = smem_u32(smem);
    const int tid  = threadIdx.x;
    const int wid  = tid >> 5;
    const int lane = tid & 31;
    const int r    = lane >> 2;
    const int qc   = lane & 3;

    const int bh = blockIdx.x;
    const int b  = bh >> 3;
    const int h  = bh & 7;

    // ---- sg for all 512 rows (fp64, one row per thread) ----
    {
        double xd = (double)sigma[((size_t)b * L_ + tid) * H_ + h];
        double sd = 1.0 / (1.0 + exp(-5.0 * xd));
        float sgm = (float)(sd + 1e-5);
        double P  = exp2((double)sgm * 1.5849625007211562);  // 3^sgm
        *(float*)(smem + PVB_SG + tid * 4) = (float)P - 1.0f;
    }

    // ---- load V (512 x 64), transpose + split into Vt hi/lo [d][s] ----
    const float* vbase = v + (size_t)b * L_ * H_ * E_ + h * E_;
#pragma unroll
    for (int i = tid; i < 8192; i += 512) {
        int s = i >> 4, d4 = i & 15;
        float4 vv = *(const float4*)(vbase + (size_t)s * (H_ * E_) + d4 * 4);
        float xs[4] = {vv.x, vv.y, vv.z, vv.w};
#pragma unroll
        for (int j = 0; j < 4; j++) {
            __nv_bfloat16 hb = __float2bfloat16(xs[j]);
            float hf = __bfloat162float(hb);
            __nv_bfloat16 lb = __float2bfloat16(xs[j] - hf);
            uint32_t off = (uint32_t)(d4 * 4 + j) * PVB_ST + s * 2;
            *(__nv_bfloat16*)(smem + PVB_HI + off) = hb;
            *(__nv_bfloat16*)(smem + PVB_LO + off) = lb;
        }
    }
    __syncthreads();

    const float* prow = p + ((size_t)bh * L_ + wid * 32) * L_;

    float acc[2][8][4];
#pragma unroll
    for (int m = 0; m < 2; m++)
#pragma unroll
        for (int nb = 0; nb < 8; nb++)
#pragma unroll
            for (int x = 0; x < 4; x++) acc[m][nb][x] = 0.f;

#pragma unroll 2
    for (int ks = 0; ks < 32; ks++) {
        // (1) issue P fragment loads (long latency)
        const int c0 = ks * 16 + qc * 2;
        float2 x0[2], x1[2], x2[2], x3[2];
#pragma unroll
        for (int m = 0; m < 2; m++) {
            x0[m] = *(const float2*)(prow + (size_t)(m * 16 + r) * L_ + c0);
            x1[m] = *(const float2*)(prow + (size_t)(m * 16 + r + 8) * L_ + c0);
            x2[m] = *(const float2*)(prow + (size_t)(m * 16 + r) * L_ + c0 + 8);
            x3[m] = *(const float2*)(prow + (size_t)(m * 16 + r + 8) * L_ + c0 + 8);
        }

        // (2) prior + sigf slice for rows [ks*16, ks*16+16) — hides P latency
        {
            const int row = ks * 16 + (tid >> 5);      // one row per warp
            const int j0  = lane * 16;                 // 16 cols per thread
            const float sg = *(const float*)(smem + PVB_SG + row * 4);
            const float cv   = __fdiv_rn(0.3989422804014327f, sg);
            const float rinv = __fdiv_rn(1.0f, __fmul_rn(2.0f, __fmul_rn(sg, sg)));
            const float4 sgv = make_float4(sg, sg, sg, sg);
            size_t base = ((size_t)bh * L_ + row) * L_ + j0;
#pragma unroll
            for (int t = 0; t < 4; t++) {
                int j = j0 + t * 4;
                float d0 = (float)(row - j);
                float d1 = (float)(row - j - 1);
                float d2 = (float)(row - j - 2);
                float d3 = (float)(row - j - 3);
                float4 pv;
                pv.x = __fmul_rn(cv, exp_acc(-__fmul_rn(__fmul_rn(d0, d0), rinv)));
                pv.y = __fmul_rn(cv, exp_acc(-__fmul_rn(__fmul_rn(d1, d1), rinv)));
                pv.z = __fmul_rn(cv, exp_acc(-__fmul_rn(__fmul_rn(d2, d2), rinv)));
                pv.w = __fmul_rn(cv, exp_acc(-__fmul_rn(__fmul_rn(d3, d3), rinv)));
                *(float4*)(prior + base + t * 4) = pv;
                *(float4*)(sigf + base + t * 4)  = sgv;
            }
        }

        // (3) split P to bf16 hi/lo
        uint32_t ahi[2][4], alo[2][4];
#pragma unroll
        for (int m = 0; m < 2; m++) {
            split2(x0[m], ahi[m][0], alo[m][0]);
            split2(x1[m], ahi[m][1], alo[m][1]);
            split2(x2[m], ahi[m][2], alo[m][2]);
            split2(x3[m], ahi[m][3], alo[m][3]);
        }

        // (4) MMA
        const uint32_t kByte = (uint32_t)ks * 32 + qc * 4;
#pragma unroll
        for (int nb = 0; nb < 8; nb++) {
            uint32_t bd = sb + (uint32_t)(nb * 8 + r) * PVB_ST + kByte;
            uint32_t bhi[2], blo[2];
            bhi[0] = lds32(bd + PVB_HI);
            bhi[1] = lds32(bd + PVB_HI + 16);
            blo[0] = lds32(bd + PVB_LO);
            blo[1] = lds32(bd + PVB_LO + 16);
#pragma unroll
            for (int m = 0; m < 2; m++) {
                mma16816(acc[m][nb], ahi[m], bhi);
                mma16816(acc[m][nb], alo[m], bhi);
                mma16816(acc[m][nb], ahi[m], blo);
            }
        }
    }

    // ---- epilogue: V out ----
#pragma unroll
    for (int m = 0; m < 2; m++) {
        const int l0 = wid * 32 + m * 16 + r;
        float* ob0 = out + (((size_t)b * L_ + l0) * H_ + h) * E_ + qc * 2;
        float* ob1 = out + (((size_t)b * L_ + l0 + 8) * H_ + h) * E_ + qc * 2;
#pragma unroll
        for (int nb = 0; nb < 8; nb++) {
            *(float2*)(ob0 + nb * 8) = make_float2(acc[m][nb][0], acc[m][nb][1]);
            *(float2*)(ob1 + nb * 8) = make_float2(acc[m][nb][2], acc[m][nb][3]);
        }
    }
}

// ======================================================================
extern "C" void kernel_launch(void* const* d_in, const int* in_sizes, int n_in,
                              void* d_out, int out_size)
{
    const float* q     = (const float*)d_in[0];
    const float* k     = (const float*)d_in[1];
    const float* v     = (const float*)d_in[2];
    const float* sigma = (const float*)d_in[3];

    float* out    = (float*)d_out;
    float* Vout   = out;                                        // [B,L,H,E]
    float* series = Vout + (size_t)B_ * L_ * H_ * E_;           // [B,H,L,L]
    float* prior  = series + (size_t)BH_ * L_ * L_;             // [B,H,L,L]
    float* sigf   = prior + (size_t)BH_ * L_ * L_;              // [B,H,L,L]

    cudaFuncSetAttribute(qk_softmax_kernel, cudaFuncAttributeMaxDynamicSharedMemorySize, F_SMEM);
    cudaFuncSetAttribute(pv4_kernel, cudaFuncAttributeMaxDynamicSharedMemorySize, PVB_SMEM);

    dim3 g1(8, BH_);
    qk_softmax_kernel<<<g1, 512, F_SMEM>>>(q, k, series);

    pv4_kernel<<<BH_, 512, PVB_SMEM>>>(series, v, sigma, Vout, prior, sigf);
}

// round 14
// speedup vs baseline: 1.1467x; 1.1467x over previous
#include <cuda_runtime.h>
#include <cuda_bf16.h>
#include <cstdint>

// Problem dims
#define B_ 16
#define L_ 512
#define H_ 8
#define E_ 64
#define BH_ (B_ * H_)          // 128

// ===================== helpers =====================
__device__ __forceinline__ uint32_t smem_u32(const void* p) {
    uint32_t a;
    asm("{ .reg .u64 t; cvta.to.shared.u64 t, %1; cvt.u32.u64 %0, t; }"
        : "=r"(a) : "l"(p));
    return a;
}
__device__ __forceinline__ uint32_t bf16x2_of(float v0, float v1) {
    uint32_t r;
    asm("cvt.rn.bf16x2.f32 %0, %1, %2;" : "=r"(r) : "f"(v1), "f"(v0));
    return r;
}
__device__ __forceinline__ uint32_t lds32(uint32_t addr) {
    uint32_t v;
    asm volatile("ld.shared.b32 %0, [%1];" : "=r"(v) : "r"(addr));
    return v;
}
__device__ __forceinline__ float2 lds64f(uint32_t addr) {
    float2 v;
    asm volatile("ld.shared.v2.f32 {%0,%1}, [%2];"
                 : "=f"(v.x), "=f"(v.y) : "r"(addr));
    return v;
}
__device__ __forceinline__ void mma16816(float* c, const uint32_t* a, const uint32_t* b) {
    asm volatile(
        "mma.sync.aligned.m16n8k16.row.col.f32.bf16.bf16.f32 "
        "{%0,%1,%2,%3}, {%4,%5,%6,%7}, {%8,%9}, {%0,%1,%2,%3};"
        : "+f"(c[0]), "+f"(c[1]), "+f"(c[2]), "+f"(c[3])
        : "r"(a[0]), "r"(a[1]), "r"(a[2]), "r"(a[3]), "r"(b[0]), "r"(b[1]));
}
__device__ __forceinline__ float exp_acc(float x) {
    float m = __fmul_rn(x, 1.4426950408889634f);
    float t = __fmaf_rn(x, 1.925962991e-8f, m);
    float r;
    asm("ex2.approx.ftz.f32 %0, %1;" : "=f"(r) : "f"(t));
    return r;
}
__device__ __forceinline__ void split_store4(char* smem, uint32_t offHi, uint32_t offLo, float4 v) {
    uint32_t h01 = bf16x2_of(v.x, v.y);
    uint32_t h23 = bf16x2_of(v.z, v.w);
    float l0 = v.x - __uint_as_float(h01 << 16);
    float l1 = v.y - __uint_as_float(h01 & 0xFFFF0000u);
    float l2 = v.z - __uint_as_float(h23 << 16);
    float l3 = v.w - __uint_as_float(h23 & 0xFFFF0000u);
    *(uint2*)(smem + offHi) = make_uint2(h01, h23);
    *(uint2*)(smem + offLo) = make_uint2(bf16x2_of(l0, l1), bf16x2_of(l2, l3));
}
__device__ __forceinline__ void split2(float2 v, uint32_t& hi, uint32_t& lo) {
    hi = bf16x2_of(v.x, v.y);
    float l0 = v.x - __uint_as_float(hi << 16);
    float l1 = v.y - __uint_as_float(hi & 0xFFFF0000u);
    lo = bf16x2_of(l0, l1);
}
#define CP_ASYNC16(dst, src) \
    asm volatile("cp.async.ca.shared.global [%0], [%1], 16;" :: "r"(dst), "l"(src) : "memory")
#define CP_COMMIT() asm volatile("cp.async.commit_group;" ::: "memory")
#define CP_WAIT1()  asm volatile("cp.async.wait_group 1;" ::: "memory")
#define CP_WAIT0()  asm volatile("cp.async.wait_group 0;" ::: "memory")

// ======================================================================
// Kernel 1 (exact R9, measured as part of 163.2us): sg (fp64) ->
// Q/K load -> prior+sigf (drains during MMA) -> QK^T MMA -> softmax.
// ======================================================================
#define F_ST   72
#define F_QHI  0
#define F_QLO  9216
#define F_KHI  18432
#define F_KLO  92160
#define F_SG   165888
#define F_RED0 166144
#define F_RED1 167168
#define F_SMEM 168192

__global__ void __launch_bounds__(512, 1)
qk_softmax_prior_kernel(const float* __restrict__ q, const float* __restrict__ k,
                        const float* __restrict__ sigma,
                        float* __restrict__ series,
                        float* __restrict__ prior, float* __restrict__ sigf)
{
    extern __shared__ char smem[];
    const uint32_t sb = smem_u32(smem);
    const int tid  = threadIdx.x;
    const int wid  = tid >> 5;
    const int lane = tid & 31;
    const int wm   = wid >> 2;
    const int wn   = wid & 3;
    const int r    = lane >> 2;
    const int qc   = lane & 3;

    const int bh = blockIdx.y;
    const int b  = bh >> 3;
    const int h  = bh & 7;
    const int lt = blockIdx.x;
    const int lbase = lt * 64;

    if (tid < 64) {
        int gl = lbase + tid;
        double xd = (double)sigma[((size_t)b * L_ + gl) * H_ + h];
        double sd = 1.0 / (1.0 + exp(-5.0 * xd));
        float sgm = (float)(sd + 1e-5);
        double P  = exp2((double)sgm * 1.5849625007211562);  // 3^sgm
        *(float*)(smem + F_SG + tid * 4) = (float)P - 1.0f;
    }

    const float* qbase = q + (size_t)(b * L_ + lbase) * (H_ * E_) + h * E_;
    const float* kbase = k + (size_t)(b * L_) * (H_ * E_) + h * E_;

#pragma unroll
    for (int i = tid; i < 1024; i += 512) {
        int row = i >> 4, e4 = i & 15;
        uint32_t off = (uint32_t)row * (F_ST * 2) + e4 * 8;
        float4 va = *(const float4*)(qbase + (size_t)row * (H_ * E_) + e4 * 4);
        va.x *= 0.125f; va.y *= 0.125f; va.z *= 0.125f; va.w *= 0.125f;
        split_store4(smem, F_QHI + off, F_QLO + off, va);
    }
#pragma unroll
    for (int i = tid; i < 8192; i += 512) {
        int row = i >> 4, e4 = i & 15;
        uint32_t off = (uint32_t)row * (F_ST * 2) + e4 * 8;
        float4 vb = *(const float4*)(kbase + (size_t)row * (H_ * E_) + e4 * 4);
        split_store4(smem, F_KHI + off, F_KLO + off, vb);
    }
    __syncthreads();

    // prior + sigma_full (stores drain during MMA phase)
    {
#pragma unroll
        for (int i = tid; i < 8192; i += 512) {
            int row = i >> 7, c4 = (i & 127) * 4;
            const float sg = *(const float*)(smem + F_SG + row * 4);
            const float cv   = __fdiv_rn(0.3989422804014327f, sg);
            const float rinv = __fdiv_rn(1.0f, __fmul_rn(2.0f, __fmul_rn(sg, sg)));
            const int gl = lbase + row;
            float d0 = (float)(gl - c4);
            float d1 = (float)(gl - c4 - 1);
            float d2 = (float)(gl - c4 - 2);
            float d3 = (float)(gl - c4 - 3);
            float4 pv;
            pv.x = __fmul_rn(cv, exp_acc(-__fmul_rn(__fmul_rn(d0, d0), rinv)));
            pv.y = __fmul_rn(cv, exp_acc(-__fmul_rn(__fmul_rn(d1, d1), rinv)));
            pv.z = __fmul_rn(cv, exp_acc(-__fmul_rn(__fmul_rn(d2, d2), rinv)));
            pv.w = __fmul_rn(cv, exp_acc(-__fmul_rn(__fmul_rn(d3, d3), rinv)));
            size_t base = ((size_t)bh * L_ + gl) * L_ + c4;
            *(float4*)(prior + base) = pv;
            *(float4*)(sigf + base)  = make_float4(sg, sg, sg, sg);
        }
    }

    float acc[16][4];
#pragma unroll
    for (int nb = 0; nb < 16; nb++)
#pragma unroll
        for (int x = 0; x < 4; x++) acc[nb][x] = 0.f;

    {
        const uint32_t abase[3] = {sb + F_QHI, sb + F_QHI, sb + F_QLO};
        const uint32_t bbase[3] = {sb + F_KHI, sb + F_KLO, sb + F_KHI};
#pragma unroll
        for (int pr = 0; pr < 3; pr++) {
            uint32_t Ab = abase[pr], Bb = bbase[pr];
#pragma unroll
            for (int ks = 0; ks < 4; ks++) {
                uint32_t kByte = ks * 32 + qc * 4;
                uint32_t a[4];
                uint32_t ad = Ab + (uint32_t)(wm * 16 + r) * (F_ST * 2) + kByte;
                a[0] = lds32(ad);
                a[1] = lds32(ad + 8 * F_ST * 2);
                a[2] = lds32(ad + 16);
                a[3] = lds32(ad + 8 * F_ST * 2 + 16);
#pragma unroll
                for (int nb = 0; nb < 16; nb++) {
                    uint32_t bd = Bb + (uint32_t)(wn * 128 + nb * 8 + r) * (F_ST * 2) + kByte;
                    uint32_t bf[2];
                    bf[0] = lds32(bd);
                    bf[1] = lds32(bd + 16);
                    mma16816(acc[nb], a, bf);
                }
            }
        }
    }

    const int row0 = wm * 16 + r;
    const int row1 = row0 + 8;

    float mx0 = -1e30f, mx1 = -1e30f;
#pragma unroll
    for (int nb = 0; nb < 16; nb++) {
        mx0 = fmaxf(mx0, fmaxf(acc[nb][0], acc[nb][1]));
        mx1 = fmaxf(mx1, fmaxf(acc[nb][2], acc[nb][3]));
    }
#pragma unroll
    for (int o = 1; o <= 2; o <<= 1) {
        mx0 = fmaxf(mx0, __shfl_xor_sync(0xffffffffu, mx0, o));
        mx1 = fmaxf(mx1, __shfl_xor_sync(0xffffffffu, mx1, o));
    }
    if (qc == 0) {
        *(float*)(smem + F_RED0 + (row0 * 4 + wn) * 4) = mx0;
        *(float*)(smem + F_RED0 + (row1 * 4 + wn) * 4) = mx1;
    }
    __syncthreads();
    {
        const float* rd = (const float*)(smem + F_RED0);
        mx0 = fmaxf(fmaxf(rd[row0 * 4 + 0], rd[row0 * 4 + 1]),
                    fmaxf(rd[row0 * 4 + 2], rd[row0 * 4 + 3]));
        mx1 = fmaxf(fmaxf(rd[row1 * 4 + 0], rd[row1 * 4 + 1]),
                    fmaxf(rd[row1 * 4 + 2], rd[row1 * 4 + 3]));
    }

    float s0 = 0.f, s1 = 0.f;
#pragma unroll
    for (int nb = 0; nb < 16; nb++) {
        acc[nb][0] = exp_acc(acc[nb][0] - mx0); s0 += acc[nb][0];
        acc[nb][1] = exp_acc(acc[nb][1] - mx0); s0 += acc[nb][1];
        acc[nb][2] = exp_acc(acc[nb][2] - mx1); s1 += acc[nb][2];
        acc[nb][3] = exp_acc(acc[nb][3] - mx1); s1 += acc[nb][3];
    }
#pragma unroll
    for (int o = 1; o <= 2; o <<= 1) {
        s0 += __shfl_xor_sync(0xffffffffu, s0, o);
        s1 += __shfl_xor_sync(0xffffffffu, s1, o);
    }
    if (qc == 0) {
        *(float*)(smem + F_RED1 + (row0 * 4 + wn) * 4) = s0;
        *(float*)(smem + F_RED1 + (row1 * 4 + wn) * 4) = s1;
    }
    __syncthreads();
    {
        const float* rd = (const float*)(smem + F_RED1);
        s0 = (rd[row0 * 4 + 0] + rd[row0 * 4 + 1]) + (rd[row0 * 4 + 2] + rd[row0 * 4 + 3]);
        s1 = (rd[row1 * 4 + 0] + rd[row1 * 4 + 1]) + (rd[row1 * 4 + 2] + rd[row1 * 4 + 3]);
    }
    const float inv0 = __fdiv_rn(1.f, s0);
    const float inv1 = __fdiv_rn(1.f, s1);

    float* o0 = series + ((size_t)bh * L_ + lbase + row0) * L_ + wn * 128 + qc * 2;
    float* o1 = series + ((size_t)bh * L_ + lbase + row1) * L_ + wn * 128 + qc * 2;
#pragma unroll
    for (int nb = 0; nb < 16; nb++) {
        *(float2*)(o0 + nb * 8) = make_float2(acc[nb][0] * inv0, acc[nb][1] * inv0);
        *(float2*)(o1 + nb * 8) = make_float2(acc[nb][2] * inv1, acc[nb][3] * inv1);
    }
}

// ======================================================================
// Kernel 2 (pv5): V = P @ values with cp.async double-buffered P stage.
// One CTA per bh: 512 rows x 64 d, 512 thr, warp = 32 rows.
// Each warp stages its own 32-row x 16-col P slice (80B row stride,
// 16B-aligned); LDGSTS depth-2 pipeline, no extra registers.
// ======================================================================
#define PVB_ST    1040
#define PVB_HI    0
#define PVB_LO    66560
#define PV5_STAGE 133120           // 2 bufs x 512 rows x 80 B = 81920
#define PV5_BUF   40960
#define PV5_SMEM  215040

__global__ void __launch_bounds__(512, 1)
pv5_kernel(const float* __restrict__ p, const float* __restrict__ v,
           float* __restrict__ out)
{
    extern __shared__ char smem[];
    const uint32_t sb = smem_u32(smem);
    const int tid  = threadIdx.x;
    const int wid  = tid >> 5;
    const int lane = tid & 31;
    const int r    = lane >> 2;
    const int qc   = lane & 3;

    const int bh = blockIdx.x;
    const int b  = bh >> 3;
    const int h  = bh & 7;

    // ---- load V (512 x 64), transpose + split into Vt hi/lo [d][s] ----
    const float* vbase = v + (size_t)b * L_ * H_ * E_ + h * E_;
#pragma unroll
    for (int i = tid; i < 8192; i += 512) {
        int s = i >> 4, d4 = i & 15;
        float4 vv = *(const float4*)(vbase + (size_t)s * (H_ * E_) + d4 * 4);
        float xs[4] = {vv.x, vv.y, vv.z, vv.w};
#pragma unroll
        for (int j = 0; j < 4; j++) {
            __nv_bfloat16 hb = __float2bfloat16(xs[j]);
            float hf = __bfloat162float(hb);
            __nv_bfloat16 lb = __float2bfloat16(xs[j] - hf);
            uint32_t off = (uint32_t)(d4 * 4 + j) * PVB_ST + s * 2;
            *(__nv_bfloat16*)(smem + PVB_HI + off) = hb;
            *(__nv_bfloat16*)(smem + PVB_LO + off) = lb;
        }
    }
    __syncthreads();

    const float* pwarp = p + ((size_t)bh * L_ + wid * 32) * L_;
    const uint32_t stw = sb + PV5_STAGE + (uint32_t)(wid * 32) * 80;

    float acc[2][8][4];
#pragma unroll
    for (int m = 0; m < 2; m++)
#pragma unroll
        for (int nb = 0; nb < 8; nb++)
#pragma unroll
            for (int x = 0; x < 4; x++) acc[m][nb][x] = 0.f;

    // stage chunk ks into buffer buf (each warp stages its own 32 rows)
    auto do_stage = [&](int ks, int buf) {
#pragma unroll
        for (int i = 0; i < 4; i++) {
            int c = lane + 32 * i;          // 128 chunks of 16B
            int row = c >> 2, seg = c & 3;
            const float* src = pwarp + (size_t)row * L_ + ks * 16 + seg * 4;
            uint32_t dst = stw + (uint32_t)buf * PV5_BUF + (uint32_t)row * 80 + seg * 16;
            CP_ASYNC16(dst, src);
        }
        CP_COMMIT();
    };

    do_stage(0, 0);

#pragma unroll 2
    for (int ks = 0; ks < 32; ks++) {
        const int buf = ks & 1;
        if (ks < 31) { do_stage(ks + 1, 1 - buf); CP_WAIT1(); }
        else         { CP_WAIT0(); }
        __syncwarp();

        const uint32_t cb = stw + (uint32_t)buf * PV5_BUF;
        uint32_t ahi[2][4], alo[2][4];
#pragma unroll
        for (int m = 0; m < 2; m++) {
            float2 x0 = lds64f(cb + (uint32_t)(m * 16 + r) * 80 + qc * 8);
            float2 x1 = lds64f(cb + (uint32_t)(m * 16 + r + 8) * 80 + qc * 8);
            float2 x2 = lds64f(cb + (uint32_t)(m * 16 + r) * 80 + qc * 8 + 32);
            float2 x3 = lds64f(cb + (uint32_t)(m * 16 + r + 8) * 80 + qc * 8 + 32);
            split2(x0, ahi[m][0], alo[m][0]);
            split2(x1, ahi[m][1], alo[m][1]);
            split2(x2, ahi[m][2], alo[m][2]);
            split2(x3, ahi[m][3], alo[m][3]);
        }

        const uint32_t kByte = (uint32_t)ks * 32 + qc * 4;
#pragma unroll
        for (int nb = 0; nb < 8; nb++) {
            uint32_t bd = sb + (uint32_t)(nb * 8 + r) * PVB_ST + kByte;
            uint32_t bhi[2], blo[2];
            bhi[0] = lds32(bd + PVB_HI);
            bhi[1] = lds32(bd + PVB_HI + 16);
            blo[0] = lds32(bd + PVB_LO);
            blo[1] = lds32(bd + PVB_LO + 16);
#pragma unroll
            for (int m = 0; m < 2; m++) {
                mma16816(acc[m][nb], ahi[m], bhi);
                mma16816(acc[m][nb], alo[m], bhi);
                mma16816(acc[m][nb], ahi[m], blo);
            }
        }
    }

    // ---- epilogue ----
#pragma unroll
    for (int m = 0; m < 2; m++) {
        const int l0 = wid * 32 + m * 16 + r;
        float* ob0 = out + (((size_t)b * L_ + l0) * H_ + h) * E_ + qc * 2;
        float* ob1 = out + (((size_t)b * L_ + l0 + 8) * H_ + h) * E_ + qc * 2;
#pragma unroll
        for (int nb = 0; nb < 8; nb++) {
            *(float2*)(ob0 + nb * 8) = make_float2(acc[m][nb][0], acc[m][nb][1]);
            *(float2*)(ob1 + nb * 8) = make_float2(acc[m][nb][2], acc[m][nb][3]);
        }
    }
}

// ======================================================================
extern "C" void kernel_launch(void* const* d_in, const int* in_sizes, int n_in,
                              void* d_out, int out_size)
{
    const float* q     = (const float*)d_in[0];
    const float* k     = (const float*)d_in[1];
    const float* v     = (const float*)d_in[2];
    const float* sigma = (const float*)d_in[3];

    float* out    = (float*)d_out;
    float* Vout   = out;                                        // [B,L,H,E]
    float* series = Vout + (size_t)B_ * L_ * H_ * E_;           // [B,H,L,L]
    float* prior  = series + (size_t)BH_ * L_ * L_;             // [B,H,L,L]
    float* sigf   = prior + (size_t)BH_ * L_ * L_;              // [B,H,L,L]

    cudaFuncSetAttribute(qk_softmax_prior_kernel, cudaFuncAttributeMaxDynamicSharedMemorySize, F_SMEM);
    cudaFuncSetAttribute(pv5_kernel, cudaFuncAttributeMaxDynamicSharedMemorySize, PV5_SMEM);

    dim3 g1(8, BH_);
    qk_softmax_prior_kernel<<<g1, 512, F_SMEM>>>(q, k, sigma, series, prior, sigf);

    pv5_kernel<<<BH_, 512, PV5_SMEM>>>(series, v, Vout);
}

// round 15
// speedup vs baseline: 1.2103x; 1.0555x over previous
#include <cuda_runtime.h>
#include <cuda_bf16.h>
#include <cstdint>

// Problem dims
#define B_ 16
#define L_ 512
#define H_ 8
#define E_ 64
#define BH_ (B_ * H_)          // 128

// ===================== helpers =====================
__device__ __forceinline__ uint32_t smem_u32(const void* p) {
    uint32_t a;
    asm("{ .reg .u64 t; cvta.to.shared.u64 t, %1; cvt.u32.u64 %0, t; }"
        : "=r"(a) : "l"(p));
    return a;
}
__device__ __forceinline__ uint32_t bf16x2_of(float v0, float v1) {
    uint32_t r;
    asm("cvt.rn.bf16x2.f32 %0, %1, %2;" : "=r"(r) : "f"(v1), "f"(v0));
    return r;
}
__device__ __forceinline__ uint32_t lds32(uint32_t addr) {
    uint32_t v;
    asm volatile("ld.shared.b32 %0, [%1];" : "=r"(v) : "r"(addr));
    return v;
}
__device__ __forceinline__ void mma16816(float* c, const uint32_t* a, const uint32_t* b) {
    asm volatile(
        "mma.sync.aligned.m16n8k16.row.col.f32.bf16.bf16.f32 "
        "{%0,%1,%2,%3}, {%4,%5,%6,%7}, {%8,%9}, {%0,%1,%2,%3};"
        : "+f"(c[0]), "+f"(c[1]), "+f"(c[2]), "+f"(c[3])
        : "r"(a[0]), "r"(a[1]), "r"(a[2]), "r"(a[3]), "r"(b[0]), "r"(b[1]));
}
__device__ __forceinline__ float exp_acc(float x) {
    float m = __fmul_rn(x, 1.4426950408889634f);
    float t = __fmaf_rn(x, 1.925962991e-8f, m);
    float r;
    asm("ex2.approx.ftz.f32 %0, %1;" : "=f"(r) : "f"(t));
    return r;
}
__device__ __forceinline__ void split_store4(char* smem, uint32_t offHi, uint32_t offLo, float4 v) {
    uint32_t h01 = bf16x2_of(v.x, v.y);
    uint32_t h23 = bf16x2_of(v.z, v.w);
    float l0 = v.x - __uint_as_float(h01 << 16);
    float l1 = v.y - __uint_as_float(h01 & 0xFFFF0000u);
    float l2 = v.z - __uint_as_float(h23 << 16);
    float l3 = v.w - __uint_as_float(h23 & 0xFFFF0000u);
    *(uint2*)(smem + offHi) = make_uint2(h01, h23);
    *(uint2*)(smem + offLo) = make_uint2(bf16x2_of(l0, l1), bf16x2_of(l2, l3));
}
__device__ __forceinline__ void split2(float2 v, uint32_t& hi, uint32_t& lo) {
    hi = bf16x2_of(v.x, v.y);
    float l0 = v.x - __uint_as_float(hi << 16);
    float l1 = v.y - __uint_as_float(hi & 0xFFFF0000u);
    lo = bf16x2_of(l0, l1);
}

// ======================================================================
// Kernel 1: R9 structure; MMA loop restructured to load A/B fragments
// once per ks/nb and issue the 3 split-product MMAs back-to-back
// (33% fewer LDS in the hot loop).
// ======================================================================
#define F_ST   72
#define F_QHI  0
#define F_QLO  9216
#define F_KHI  18432
#define F_KLO  92160
#define F_SG   165888
#define F_RED0 166144
#define F_RED1 167168
#define F_SMEM 168192

__global__ void __launch_bounds__(512, 1)
qk_softmax_prior_kernel(const float* __restrict__ q, const float* __restrict__ k,
                        const float* __restrict__ sigma,
                        float* __restrict__ series,
                        float* __restrict__ prior, float* __restrict__ sigf)
{
    extern __shared__ char smem[];
    const uint32_t sb = smem_u32(smem);
    const int tid  = threadIdx.x;
    const int wid  = tid >> 5;
    const int lane = tid & 31;
    const int wm   = wid >> 2;
    const int wn   = wid & 3;
    const int r    = lane >> 2;
    const int qc   = lane & 3;

    const int bh = blockIdx.y;
    const int b  = bh >> 3;
    const int h  = bh & 7;
    const int lt = blockIdx.x;
    const int lbase = lt * 64;

    // ---- sigma -> bandwidth (fp64, 64 threads) ----
    if (tid < 64) {
        int gl = lbase + tid;
        double xd = (double)sigma[((size_t)b * L_ + gl) * H_ + h];
        double sd = 1.0 / (1.0 + exp(-5.0 * xd));
        float sgm = (float)(sd + 1e-5);
        double P  = exp2((double)sgm * 1.5849625007211562);  // 3^sgm
        *(float*)(smem + F_SG + tid * 4) = (float)P - 1.0f;
    }

    const float* qbase = q + (size_t)(b * L_ + lbase) * (H_ * E_) + h * E_;
    const float* kbase = k + (size_t)(b * L_) * (H_ * E_) + h * E_;

#pragma unroll
    for (int i = tid; i < 1024; i += 512) {
        int row = i >> 4, e4 = i & 15;
        uint32_t off = (uint32_t)row * (F_ST * 2) + e4 * 8;
        float4 va = *(const float4*)(qbase + (size_t)row * (H_ * E_) + e4 * 4);
        va.x *= 0.125f; va.y *= 0.125f; va.z *= 0.125f; va.w *= 0.125f;
        split_store4(smem, F_QHI + off, F_QLO + off, va);
    }
#pragma unroll
    for (int i = tid; i < 8192; i += 512) {
        int row = i >> 4, e4 = i & 15;
        uint32_t off = (uint32_t)row * (F_ST * 2) + e4 * 8;
        float4 vb = *(const float4*)(kbase + (size_t)row * (H_ * E_) + e4 * 4);
        split_store4(smem, F_KHI + off, F_KLO + off, vb);
    }
    __syncthreads();

    // ---- prior + sigma_full (stores drain during MMA phase) ----
    {
#pragma unroll
        for (int i = tid; i < 8192; i += 512) {
            int row = i >> 7, c4 = (i & 127) * 4;
            const float sg = *(const float*)(smem + F_SG + row * 4);
            const float cv   = __fdiv_rn(0.3989422804014327f, sg);
            const float rinv = __fdiv_rn(1.0f, __fmul_rn(2.0f, __fmul_rn(sg, sg)));
            const int gl = lbase + row;
            float d0 = (float)(gl - c4);
            float d1 = (float)(gl - c4 - 1);
            float d2 = (float)(gl - c4 - 2);
            float d3 = (float)(gl - c4 - 3);
            float4 pv;
            pv.x = __fmul_rn(cv, exp_acc(-__fmul_rn(__fmul_rn(d0, d0), rinv)));
            pv.y = __fmul_rn(cv, exp_acc(-__fmul_rn(__fmul_rn(d1, d1), rinv)));
            pv.z = __fmul_rn(cv, exp_acc(-__fmul_rn(__fmul_rn(d2, d2), rinv)));
            pv.w = __fmul_rn(cv, exp_acc(-__fmul_rn(__fmul_rn(d3, d3), rinv)));
            size_t base = ((size_t)bh * L_ + gl) * L_ + c4;
            *(float4*)(prior + base) = pv;
            *(float4*)(sigf + base)  = make_float4(sg, sg, sg, sg);
        }
    }

    // ---- QK^T MMA: load frags once, 3 MMAs per (ks, nb) ----
    float acc[16][4];
#pragma unroll
    for (int nb = 0; nb < 16; nb++)
#pragma unroll
        for (int x = 0; x < 4; x++) acc[nb][x] = 0.f;

#pragma unroll
    for (int ks = 0; ks < 4; ks++) {
        uint32_t kByte = ks * 32 + qc * 4;
        uint32_t ahi[4], alo[4];
        {
            uint32_t ad = sb + F_QHI + (uint32_t)(wm * 16 + r) * (F_ST * 2) + kByte;
            ahi[0] = lds32(ad);
            ahi[1] = lds32(ad + 8 * F_ST * 2);
            ahi[2] = lds32(ad + 16);
            ahi[3] = lds32(ad + 8 * F_ST * 2 + 16);
            uint32_t al = ad + (F_QLO - F_QHI);
            alo[0] = lds32(al);
            alo[1] = lds32(al + 8 * F_ST * 2);
            alo[2] = lds32(al + 16);
            alo[3] = lds32(al + 8 * F_ST * 2 + 16);
        }
#pragma unroll
        for (int nb = 0; nb < 16; nb++) {
            uint32_t bd = sb + F_KHI + (uint32_t)(wn * 128 + nb * 8 + r) * (F_ST * 2) + kByte;
            uint32_t bhi[2], blo[2];
            bhi[0] = lds32(bd);
            bhi[1] = lds32(bd + 16);
            blo[0] = lds32(bd + (F_KLO - F_KHI));
            blo[1] = lds32(bd + (F_KLO - F_KHI) + 16);
            mma16816(acc[nb], ahi, bhi);
            mma16816(acc[nb], ahi, blo);
            mma16816(acc[nb], alo, bhi);
        }
    }

    // ---- softmax over 512 cols ----
    const int row0 = wm * 16 + r;
    const int row1 = row0 + 8;

    float mx0 = -1e30f, mx1 = -1e30f;
#pragma unroll
    for (int nb = 0; nb < 16; nb++) {
        mx0 = fmaxf(mx0, fmaxf(acc[nb][0], acc[nb][1]));
        mx1 = fmaxf(mx1, fmaxf(acc[nb][2], acc[nb][3]));
    }
#pragma unroll
    for (int o = 1; o <= 2; o <<= 1) {
        mx0 = fmaxf(mx0, __shfl_xor_sync(0xffffffffu, mx0, o));
        mx1 = fmaxf(mx1, __shfl_xor_sync(0xffffffffu, mx1, o));
    }
    if (qc == 0) {
        *(float*)(smem + F_RED0 + (row0 * 4 + wn) * 4) = mx0;
        *(float*)(smem + F_RED0 + (row1 * 4 + wn) * 4) = mx1;
    }
    __syncthreads();
    {
        const float* rd = (const float*)(smem + F_RED0);
        mx0 = fmaxf(fmaxf(rd[row0 * 4 + 0], rd[row0 * 4 + 1]),
                    fmaxf(rd[row0 * 4 + 2], rd[row0 * 4 + 3]));
        mx1 = fmaxf(fmaxf(rd[row1 * 4 + 0], rd[row1 * 4 + 1]),
                    fmaxf(rd[row1 * 4 + 2], rd[row1 * 4 + 3]));
    }

    float s0 = 0.f, s1 = 0.f;
#pragma unroll
    for (int nb = 0; nb < 16; nb++) {
        acc[nb][0] = exp_acc(acc[nb][0] - mx0); s0 += acc[nb][0];
        acc[nb][1] = exp_acc(acc[nb][1] - mx0); s0 += acc[nb][1];
        acc[nb][2] = exp_acc(acc[nb][2] - mx1); s1 += acc[nb][2];
        acc[nb][3] = exp_acc(acc[nb][3] - mx1); s1 += acc[nb][3];
    }
#pragma unroll
    for (int o = 1; o <= 2; o <<= 1) {
        s0 += __shfl_xor_sync(0xffffffffu, s0, o);
        s1 += __shfl_xor_sync(0xffffffffu, s1, o);
    }
    if (qc == 0) {
        *(float*)(smem + F_RED1 + (row0 * 4 + wn) * 4) = s0;
        *(float*)(smem + F_RED1 + (row1 * 4 + wn) * 4) = s1;
    }
    __syncthreads();
    {
        const float* rd = (const float*)(smem + F_RED1);
        s0 = (rd[row0 * 4 + 0] + rd[row0 * 4 + 1]) + (rd[row0 * 4 + 2] + rd[row0 * 4 + 3]);
        s1 = (rd[row1 * 4 + 0] + rd[row1 * 4 + 1]) + (rd[row1 * 4 + 2] + rd[row1 * 4 + 3]);
    }
    const float inv0 = __fdiv_rn(1.f, s0);
    const float inv1 = __fdiv_rn(1.f, s1);

    float* o0 = series + ((size_t)bh * L_ + lbase + row0) * L_ + wn * 128 + qc * 2;
    float* o1 = series + ((size_t)bh * L_ + lbase + row1) * L_ + wn * 128 + qc * 2;
#pragma unroll
    for (int nb = 0; nb < 16; nb++) {
        *(float2*)(o0 + nb * 8) = make_float2(acc[nb][0] * inv0, acc[nb][1] * inv0);
        *(float2*)(o1 + nb * 8) = make_float2(acc[nb][2] * inv1, acc[nb][3] * inv1);
    }
}

// ======================================================================
// Kernel 2 (pv3, exact R9 version — measured 52.9-54us): V = P @ values
// ======================================================================
#define PVB_ST  1040
#define PVB_HI  0
#define PVB_LO  66560
#define PVB_SMEM 133120

__global__ void __launch_bounds__(512, 1)
pv3_kernel(const float* __restrict__ p, const float* __restrict__ v,
           float* __restrict__ out)
{
    extern __shared__ char smem[];
    const uint32_t sb = smem_u32(smem);
    const int tid  = threadIdx.x;
    const int wid  = tid >> 5;
    const int lane = tid & 31;
    const int r    = lane >> 2;
    const int qc   = lane & 3;

    const int bh = blockIdx.x;
    const int b  = bh >> 3;
    const int h  = bh & 7;

    const float* vbase = v + (size_t)b * L_ * H_ * E_ + h * E_;

#pragma unroll
    for (int i = tid; i < 8192; i += 512) {
        int s = i >> 4, d4 = i & 15;
        float4 vv = *(const float4*)(vbase + (size_t)s * (H_ * E_) + d4 * 4);
        float xs[4] = {vv.x, vv.y, vv.z, vv.w};
#pragma unroll
        for (int j = 0; j < 4; j++) {
            __nv_bfloat16 hb = __float2bfloat16(xs[j]);
            float hf = __bfloat162float(hb);
            __nv_bfloat16 lb = __float2bfloat16(xs[j] - hf);
            uint32_t off = (uint32_t)(d4 * 4 + j) * PVB_ST + s * 2;
            *(__nv_bfloat16*)(smem + PVB_HI + off) = hb;
            *(__nv_bfloat16*)(smem + PVB_LO + off) = lb;
        }
    }
    __syncthreads();

    const float* prow = p + ((size_t)bh * L_ + wid * 32) * L_;

    float acc[2][8][4];
#pragma unroll
    for (int m = 0; m < 2; m++)
#pragma unroll
        for (int nb = 0; nb < 8; nb++)
#pragma unroll
            for (int x = 0; x < 4; x++) acc[m][nb][x] = 0.f;

#pragma unroll 2
    for (int ks = 0; ks < 32; ks++) {
        const int c0 = ks * 16 + qc * 2;
        uint32_t ahi[2][4], alo[2][4];
#pragma unroll
        for (int m = 0; m < 2; m++) {
            float2 x0 = *(const float2*)(prow + (size_t)(m * 16 + r) * L_ + c0);
            float2 x1 = *(const float2*)(prow + (size_t)(m * 16 + r + 8) * L_ + c0);
            float2 x2 = *(const float2*)(prow + (size_t)(m * 16 + r) * L_ + c0 + 8);
            float2 x3 = *(const float2*)(prow + (size_t)(m * 16 + r + 8) * L_ + c0 + 8);
            split2(x0, ahi[m][0], alo[m][0]);
            split2(x1, ahi[m][1], alo[m][1]);
            split2(x2, ahi[m][2], alo[m][2]);
            split2(x3, ahi[m][3], alo[m][3]);
        }

        const uint32_t kByte = (uint32_t)ks * 32 + qc * 4;
#pragma unroll
        for (int nb = 0; nb < 8; nb++) {
            uint32_t bd = sb + (uint32_t)(nb * 8 + r) * PVB_ST + kByte;
            uint32_t bhi[2], blo[2];
            bhi[0] = lds32(bd + PVB_HI);
            bhi[1] = lds32(bd + PVB_HI + 16);
            blo[0] = lds32(bd + PVB_LO);
            blo[1] = lds32(bd + PVB_LO + 16);
#pragma unroll
            for (int m = 0; m < 2; m++) {
                mma16816(acc[m][nb], ahi[m], bhi);
                mma16816(acc[m][nb], alo[m], bhi);
                mma16816(acc[m][nb], ahi[m], blo);
            }
        }
    }

#pragma unroll
    for (int m = 0; m < 2; m++) {
        const int l0 = wid * 32 + m * 16 + r;
        float* ob0 = out + (((size_t)b * L_ + l0) * H_ + h) * E_ + qc * 2;
        float* ob1 = out + (((size_t)b * L_ + l0 + 8) * H_ + h) * E_ + qc * 2;
#pragma unroll
        for (int nb = 0; nb < 8; nb++) {
            *(float2*)(ob0 + nb * 8) = make_float2(acc[m][nb][0], acc[m][nb][1]);
            *(float2*)(ob1 + nb * 8) = make_float2(acc[m][nb][2], acc[m][nb][3]);
        }
    }
}

// ======================================================================
extern "C" void kernel_launch(void* const* d_in, const int* in_sizes, int n_in,
                              void* d_out, int out_size)
{
    const float* q     = (const float*)d_in[0];
    const float* k     = (const float*)d_in[1];
    const float* v     = (const float*)d_in[2];
    const float* sigma = (const float*)d_in[3];

    float* out    = (float*)d_out;
    float* Vout   = out;                                        // [B,L,H,E]
    float* series = Vout + (size_t)B_ * L_ * H_ * E_;           // [B,H,L,L]
    float* prior  = series + (size_t)BH_ * L_ * L_;             // [B,H,L,L]
    float* sigf   = prior + (size_t)BH_ * L_ * L_;              // [B,H,L,L]

    cudaFuncSetAttribute(qk_softmax_prior_kernel, cudaFuncAttributeMaxDynamicSharedMemorySize, F_SMEM);
    cudaFuncSetAttribute(pv3_kernel, cudaFuncAttributeMaxDynamicSharedMemorySize, PVB_SMEM);

    dim3 g1(8, BH_);
    qk_softmax_prior_kernel<<<g1, 512, F_SMEM>>>(q, k, sigma, series, prior, sigf);

    pv3_kernel<<<BH_, 512, PVB_SMEM>>>(series, v, Vout);
}

// round 16
// speedup vs baseline: 1.2219x; 1.0096x over previous
#include <cuda_runtime.h>
#include <cuda_bf16.h>
#include <cstdint>

// Problem dims
#define B_ 16
#define L_ 512
#define H_ 8
#define E_ 64
#define BH_ (B_ * H_)          // 128

// ===================== helpers =====================
__device__ __forceinline__ uint32_t smem_u32(const void* p) {
    uint32_t a;
    asm("{ .reg .u64 t; cvta.to.shared.u64 t, %1; cvt.u32.u64 %0, t; }"
        : "=r"(a) : "l"(p));
    return a;
}
__device__ __forceinline__ uint32_t bf16x2_of(float v0, float v1) {
    uint32_t r;
    asm("cvt.rn.bf16x2.f32 %0, %1, %2;" : "=r"(r) : "f"(v1), "f"(v0));
    return r;
}
__device__ __forceinline__ uint32_t lds32(uint32_t addr) {
    uint32_t v;
    asm volatile("ld.shared.b32 %0, [%1];" : "=r"(v) : "r"(addr));
    return v;
}
__device__ __forceinline__ void mma16816(float* c, const uint32_t* a, const uint32_t* b) {
    asm volatile(
        "mma.sync.aligned.m16n8k16.row.col.f32.bf16.bf16.f32 "
        "{%0,%1,%2,%3}, {%4,%5,%6,%7}, {%8,%9}, {%0,%1,%2,%3};"
        : "+f"(c[0]), "+f"(c[1]), "+f"(c[2]), "+f"(c[3])
        : "r"(a[0]), "r"(a[1]), "r"(a[2]), "r"(a[3]), "r"(b[0]), "r"(b[1]));
}
__device__ __forceinline__ float exp_acc(float x) {
    float m = __fmul_rn(x, 1.4426950408889634f);
    float t = __fmaf_rn(x, 1.925962991e-8f, m);
    float r;
    asm("ex2.approx.ftz.f32 %0, %1;" : "=f"(r) : "f"(t));
    return r;
}
__device__ __forceinline__ void split_store4(char* smem, uint32_t offHi, uint32_t offLo, float4 v) {
    uint32_t h01 = bf16x2_of(v.x, v.y);
    uint32_t h23 = bf16x2_of(v.z, v.w);
    float l0 = v.x - __uint_as_float(h01 << 16);
    float l1 = v.y - __uint_as_float(h01 & 0xFFFF0000u);
    float l2 = v.z - __uint_as_float(h23 << 16);
    float l3 = v.w - __uint_as_float(h23 & 0xFFFF0000u);
    *(uint2*)(smem + offHi) = make_uint2(h01, h23);
    *(uint2*)(smem + offLo) = make_uint2(bf16x2_of(l0, l1), bf16x2_of(l2, l3));
}
__device__ __forceinline__ void split2(float2 v, uint32_t& hi, uint32_t& lo) {
    hi = bf16x2_of(v.x, v.y);
    float l0 = v.x - __uint_as_float(hi << 16);
    float l1 = v.y - __uint_as_float(hi & 0xFFFF0000u);
    lo = bf16x2_of(l0, l1);
}

// ======================================================================
// Kernel 1 (R15-exact + PDL trigger before series stores)
// ======================================================================
#define F_ST   72
#define F_QHI  0
#define F_QLO  9216
#define F_KHI  18432
#define F_KLO  92160
#define F_SG   165888
#define F_RED0 166144
#define F_RED1 167168
#define F_SMEM 168192

__global__ void __launch_bounds__(512, 1)
qk_softmax_prior_kernel(const float* __restrict__ q, const float* __restrict__ k,
                        const float* __restrict__ sigma,
                        float* __restrict__ series,
                        float* __restrict__ prior, float* __restrict__ sigf)
{
    extern __shared__ char smem[];
    const uint32_t sb = smem_u32(smem);
    const int tid  = threadIdx.x;
    const int wid  = tid >> 5;
    const int lane = tid & 31;
    const int wm   = wid >> 2;
    const int wn   = wid & 3;
    const int r    = lane >> 2;
    const int qc   = lane & 3;

    const int bh = blockIdx.y;
    const int b  = bh >> 3;
    const int h  = bh & 7;
    const int lt = blockIdx.x;
    const int lbase = lt * 64;

    if (tid < 64) {
        int gl = lbase + tid;
        double xd = (double)sigma[((size_t)b * L_ + gl) * H_ + h];
        double sd = 1.0 / (1.0 + exp(-5.0 * xd));
        float sgm = (float)(sd + 1e-5);
        double P  = exp2((double)sgm * 1.5849625007211562);  // 3^sgm
        *(float*)(smem + F_SG + tid * 4) = (float)P - 1.0f;
    }

    const float* qbase = q + (size_t)(b * L_ + lbase) * (H_ * E_) + h * E_;
    const float* kbase = k + (size_t)(b * L_) * (H_ * E_) + h * E_;

#pragma unroll
    for (int i = tid; i < 1024; i += 512) {
        int row = i >> 4, e4 = i & 15;
        uint32_t off = (uint32_t)row * (F_ST * 2) + e4 * 8;
        float4 va = *(const float4*)(qbase + (size_t)row * (H_ * E_) + e4 * 4);
        va.x *= 0.125f; va.y *= 0.125f; va.z *= 0.125f; va.w *= 0.125f;
        split_store4(smem, F_QHI + off, F_QLO + off, va);
    }
#pragma unroll
    for (int i = tid; i < 8192; i += 512) {
        int row = i >> 4, e4 = i & 15;
        uint32_t off = (uint32_t)row * (F_ST * 2) + e4 * 8;
        float4 vb = *(const float4*)(kbase + (size_t)row * (H_ * E_) + e4 * 4);
        split_store4(smem, F_KHI + off, F_KLO + off, vb);
    }
    __syncthreads();

    // prior + sigma_full (stores drain during MMA phase)
    {
#pragma unroll
        for (int i = tid; i < 8192; i += 512) {
            int row = i >> 7, c4 = (i & 127) * 4;
            const float sg = *(const float*)(smem + F_SG + row * 4);
            const float cv   = __fdiv_rn(0.3989422804014327f, sg);
            const float rinv = __fdiv_rn(1.0f, __fmul_rn(2.0f, __fmul_rn(sg, sg)));
            const int gl = lbase + row;
            float d0 = (float)(gl - c4);
            float d1 = (float)(gl - c4 - 1);
            float d2 = (float)(gl - c4 - 2);
            float d3 = (float)(gl - c4 - 3);
            float4 pv;
            pv.x = __fmul_rn(cv, exp_acc(-__fmul_rn(__fmul_rn(d0, d0), rinv)));
            pv.y = __fmul_rn(cv, exp_acc(-__fmul_rn(__fmul_rn(d1, d1), rinv)));
            pv.z = __fmul_rn(cv, exp_acc(-__fmul_rn(__fmul_rn(d2, d2), rinv)));
            pv.w = __fmul_rn(cv, exp_acc(-__fmul_rn(__fmul_rn(d3, d3), rinv)));
            size_t base = ((size_t)bh * L_ + gl) * L_ + c4;
            *(float4*)(prior + base) = pv;
            *(float4*)(sigf + base)  = make_float4(sg, sg, sg, sg);
        }
    }

    // QK^T MMA: load frags once, 3 MMAs per (ks, nb)
    float acc[16][4];
#pragma unroll
    for (int nb = 0; nb < 16; nb++)
#pragma unroll
        for (int x = 0; x < 4; x++) acc[nb][x] = 0.f;

#pragma unroll
    for (int ks = 0; ks < 4; ks++) {
        uint32_t kByte = ks * 32 + qc * 4;
        uint32_t ahi[4], alo[4];
        {
            uint32_t ad = sb + F_QHI + (uint32_t)(wm * 16 + r) * (F_ST * 2) + kByte;
            ahi[0] = lds32(ad);
            ahi[1] = lds32(ad + 8 * F_ST * 2);
            ahi[2] = lds32(ad + 16);
            ahi[3] = lds32(ad + 8 * F_ST * 2 + 16);
            uint32_t al = ad + (F_QLO - F_QHI);
            alo[0] = lds32(al);
            alo[1] = lds32(al + 8 * F_ST * 2);
            alo[2] = lds32(al + 16);
            alo[3] = lds32(al + 8 * F_ST * 2 + 16);
        }
#pragma unroll
        for (int nb = 0; nb < 16; nb++) {
            uint32_t bd = sb + F_KHI + (uint32_t)(wn * 128 + nb * 8 + r) * (F_ST * 2) + kByte;
            uint32_t bhi[2], blo[2];
            bhi[0] = lds32(bd);
            bhi[1] = lds32(bd + 16);
            blo[0] = lds32(bd + (F_KLO - F_KHI));
            blo[1] = lds32(bd + (F_KLO - F_KHI) + 16);
            mma16816(acc[nb], ahi, bhi);
            mma16816(acc[nb], ahi, blo);
            mma16816(acc[nb], alo, bhi);
        }
    }

    // softmax over 512 cols
    const int row0 = wm * 16 + r;
    const int row1 = row0 + 8;

    float mx0 = -1e30f, mx1 = -1e30f;
#pragma unroll
    for (int nb = 0; nb < 16; nb++) {
        mx0 = fmaxf(mx0, fmaxf(acc[nb][0], acc[nb][1]));
        mx1 = fmaxf(mx1, fmaxf(acc[nb][2], acc[nb][3]));
    }
#pragma unroll
    for (int o = 1; o <= 2; o <<= 1) {
        mx0 = fmaxf(mx0, __shfl_xor_sync(0xffffffffu, mx0, o));
        mx1 = fmaxf(mx1, __shfl_xor_sync(0xffffffffu, mx1, o));
    }
    if (qc == 0) {
        *(float*)(smem + F_RED0 + (row0 * 4 + wn) * 4) = mx0;
        *(float*)(smem + F_RED0 + (row1 * 4 + wn) * 4) = mx1;
    }
    __syncthreads();
    {
        const float* rd = (const float*)(smem + F_RED0);
        mx0 = fmaxf(fmaxf(rd[row0 * 4 + 0], rd[row0 * 4 + 1]),
                    fmaxf(rd[row0 * 4 + 2], rd[row0 * 4 + 3]));
        mx1 = fmaxf(fmaxf(rd[row1 * 4 + 0], rd[row1 * 4 + 1]),
                    fmaxf(rd[row1 * 4 + 2], rd[row1 * 4 + 3]));
    }

    float s0 = 0.f, s1 = 0.f;
#pragma unroll
    for (int nb = 0; nb < 16; nb++) {
        acc[nb][0] = exp_acc(acc[nb][0] - mx0); s0 += acc[nb][0];
        acc[nb][1] = exp_acc(acc[nb][1] - mx0); s0 += acc[nb][1];
        acc[nb][2] = exp_acc(acc[nb][2] - mx1); s1 += acc[nb][2];
        acc[nb][3] = exp_acc(acc[nb][3] - mx1); s1 += acc[nb][3];
    }
#pragma unroll
    for (int o = 1; o <= 2; o <<= 1) {
        s0 += __shfl_xor_sync(0xffffffffu, s0, o);
        s1 += __shfl_xor_sync(0xffffffffu, s1, o);
    }
    if (qc == 0) {
        *(float*)(smem + F_RED1 + (row0 * 4 + wn) * 4) = s0;
        *(float*)(smem + F_RED1 + (row1 * 4 + wn) * 4) = s1;
    }
    __syncthreads();
    {
        const float* rd = (const float*)(smem + F_RED1);
        s0 = (rd[row0 * 4 + 0] + rd[row0 * 4 + 1]) + (rd[row0 * 4 + 2] + rd[row0 * 4 + 3]);
        s1 = (rd[row1 * 4 + 0] + rd[row1 * 4 + 1]) + (rd[row1 * 4 + 2] + rd[row1 * 4 + 3]);
    }
    const float inv0 = __fdiv_rn(1.f, s0);
    const float inv1 = __fdiv_rn(1.f, s1);

    // PDL: let pv3 launch + run its V prologue while we store series.
    asm volatile("griddepcontrol.launch_dependents;" ::: "memory");

    float* o0 = series + ((size_t)bh * L_ + lbase + row0) * L_ + wn * 128 + qc * 2;
    float* o1 = series + ((size_t)bh * L_ + lbase + row1) * L_ + wn * 128 + qc * 2;
#pragma unroll
    for (int nb = 0; nb < 16; nb++) {
        *(float2*)(o0 + nb * 8) = make_float2(acc[nb][0] * inv0, acc[nb][1] * inv0);
        *(float2*)(o1 + nb * 8) = make_float2(acc[nb][2] * inv1, acc[nb][3] * inv1);
    }
}

// ======================================================================
// Kernel 2 (pv3, R9/R15-exact + PDL wait after V prologue)
// ======================================================================
#define PVB_ST  1040
#define PVB_HI  0
#define PVB_LO  66560
#define PVB_SMEM 133120

__global__ void __launch_bounds__(512, 1)
pv3_kernel(const float* __restrict__ p, const float* __restrict__ v,
           float* __restrict__ out)
{
    extern __shared__ char smem[];
    const uint32_t sb = smem_u32(smem);
    const int tid  = threadIdx.x;
    const int wid  = tid >> 5;
    const int lane = tid & 31;
    const int r    = lane >> 2;
    const int qc   = lane & 3;

    const int bh = blockIdx.x;
    const int b  = bh >> 3;
    const int h  = bh & 7;

    const float* vbase = v + (size_t)b * L_ * H_ * E_ + h * E_;

    // ---- V prologue (independent of series) runs before the PDL wait ----
#pragma unroll
    for (int i = tid; i < 8192; i += 512) {
        int s = i >> 4, d4 = i & 15;
        float4 vv = *(const float4*)(vbase + (size_t)s * (H_ * E_) + d4 * 4);
        float xs[4] = {vv.x, vv.y, vv.z, vv.w};
#pragma unroll
        for (int j = 0; j < 4; j++) {
            __nv_bfloat16 hb = __float2bfloat16(xs[j]);
            float hf = __bfloat162float(hb);
            __nv_bfloat16 lb = __float2bfloat16(xs[j] - hf);
            uint32_t off = (uint32_t)(d4 * 4 + j) * PVB_ST + s * 2;
            *(__nv_bfloat16*)(smem + PVB_HI + off) = hb;
            *(__nv_bfloat16*)(smem + PVB_LO + off) = lb;
        }
    }
    __syncthreads();

    // PDL: block until the qk grid has fully completed (series ready).
    asm volatile("griddepcontrol.wait;" ::: "memory");

    const float* prow = p + ((size_t)bh * L_ + wid * 32) * L_;

    float acc[2][8][4];
#pragma unroll
    for (int m = 0; m < 2; m++)
#pragma unroll
        for (int nb = 0; nb < 8; nb++)
#pragma unroll
            for (int x = 0; x < 4; x++) acc[m][nb][x] = 0.f;

#pragma unroll 2
    for (int ks = 0; ks < 32; ks++) {
        const int c0 = ks * 16 + qc * 2;
        uint32_t ahi[2][4], alo[2][4];
#pragma unroll
        for (int m = 0; m < 2; m++) {
            float2 x0 = *(const float2*)(prow + (size_t)(m * 16 + r) * L_ + c0);
            float2 x1 = *(const float2*)(prow + (size_t)(m * 16 + r + 8) * L_ + c0);
            float2 x2 = *(const float2*)(prow + (size_t)(m * 16 + r) * L_ + c0 + 8);
            float2 x3 = *(const float2*)(prow + (size_t)(m * 16 + r + 8) * L_ + c0 + 8);
            split2(x0, ahi[m][0], alo[m][0]);
            split2(x1, ahi[m][1], alo[m][1]);
            split2(x2, ahi[m][2], alo[m][2]);
            split2(x3, ahi[m][3], alo[m][3]);
        }

        const uint32_t kByte = (uint32_t)ks * 32 + qc * 4;
#pragma unroll
        for (int nb = 0; nb < 8; nb++) {
            uint32_t bd = sb + (uint32_t)(nb * 8 + r) * PVB_ST + kByte;
            uint32_t bhi[2], blo[2];
            bhi[0] = lds32(bd + PVB_HI);
            bhi[1] = lds32(bd + PVB_HI + 16);
            blo[0] = lds32(bd + PVB_LO);
            blo[1] = lds32(bd + PVB_LO + 16);
#pragma unroll
            for (int m = 0; m < 2; m++) {
                mma16816(acc[m][nb], ahi[m], bhi);
                mma16816(acc[m][nb], alo[m], bhi);
                mma16816(acc[m][nb], ahi[m], blo);
            }
        }
    }

#pragma unroll
    for (int m = 0; m < 2; m++) {
        const int l0 = wid * 32 + m * 16 + r;
        float* ob0 = out + (((size_t)b * L_ + l0) * H_ + h) * E_ + qc * 2;
        float* ob1 = out + (((size_t)b * L_ + l0 + 8) * H_ + h) * E_ + qc * 2;
#pragma unroll
        for (int nb = 0; nb < 8; nb++) {
            *(float2*)(ob0 + nb * 8) = make_float2(acc[m][nb][0], acc[m][nb][1]);
            *(float2*)(ob1 + nb * 8) = make_float2(acc[m][nb][2], acc[m][nb][3]);
        }
    }
}

// ======================================================================
extern "C" void kernel_launch(void* const* d_in, const int* in_sizes, int n_in,
                              void* d_out, int out_size)
{
    const float* q     = (const float*)d_in[0];
    const float* k     = (const float*)d_in[1];
    const float* v     = (const float*)d_in[2];
    const float* sigma = (const float*)d_in[3];

    float* out    = (float*)d_out;
    float* Vout   = out;                                        // [B,L,H,E]
    float* series = Vout + (size_t)B_ * L_ * H_ * E_;           // [B,H,L,L]
    float* prior  = series + (size_t)BH_ * L_ * L_;             // [B,H,L,L]
    float* sigf   = prior + (size_t)BH_ * L_ * L_;              // [B,H,L,L]

    cudaFuncSetAttribute(qk_softmax_prior_kernel, cudaFuncAttributeMaxDynamicSharedMemorySize, F_SMEM);
    cudaFuncSetAttribute(pv3_kernel, cudaFuncAttributeMaxDynamicSharedMemorySize, PVB_SMEM);

    dim3 g1(8, BH_);
    qk_softmax_prior_kernel<<<g1, 512, F_SMEM>>>(q, k, sigma, series, prior, sigf);

    // pv3 with Programmatic Dependent Launch: overlaps its V prologue with
    // qk's series-store tail; griddepcontrol.wait guards the P reads.
    cudaLaunchConfig_t cfg = {};
    cfg.gridDim = dim3(BH_, 1, 1);
    cfg.blockDim = dim3(512, 1, 1);
    cfg.dynamicSmemBytes = PVB_SMEM;
    cfg.stream = 0;
    cudaLaunchAttribute attrs[1];
    attrs[0].id = cudaLaunchAttributeProgrammaticStreamSerialization;
    attrs[0].val.programmaticStreamSerializationAllowed = 1;
    cfg.attrs = attrs;
    cfg.numAttrs = 1;
    cudaLaunchKernelEx(&cfg, pv3_kernel, (const float*)series, (const float*)v, (float*)Vout);
}